// round 14
// baseline (speedup 1.0000x reference)
#include <cuda_runtime.h>
#include <cuda_fp16.h>
#include <cstdint>
#include <cfloat>

#define B_  16384
#define TD_ 4096
#define L_  1024
#define K_  8192
#define O_  128
#define LW2 (L_ / 2)          // 512 half2 words per row

#define CAND_MAX 16
#define WIN_DOTP 2.0f         // capture window in scaled-dot units (8192*dot)

// ---------------- scratch (device globals) -----------------------------------
__device__ float    g_ze[(size_t)B_ * L_];      // 64 MB fp32 z_e
__device__ float    g_zq[(size_t)B_ * L_];      // 64 MB fp32 z_q
__device__ float    g_dotf[(size_t)B_ * K_];    // 512 MB scaled approx dots
__device__ __half2  g_zh[(size_t)B_ * LW2];     // 32 MB packed half2 z
__device__ __half2  g_cbh[(size_t)K_ * LW2];    // 16 MB packed half2 codebook*8192
__device__ float    g_P[B_];
__device__ float    g_c[K_];
__device__ uint32_t g_rowmax[B_];               // monotonic float keys
__device__ int      g_idx[B_];
__device__ int      g_cand2[(size_t)B_ * CAND_MAX];
__device__ int      g_ncand[B_];
__device__ double   g_rowloss[B_];

// packed fp32x2 FMA: two IEEE-rn fp32 FMAs per instruction (sm_100+)
#define FMA_X2(acc, a, b) \
    asm("fma.rn.f32x2 %0, %1, %2, %0;" : "+l"(acc) : "l"(a), "l"(b))
__device__ __forceinline__ void unpack_x2(unsigned long long v, float& lo, float& hi) {
    asm("mov.b64 {%0, %1}, %2;" : "=f"(lo), "=f"(hi) : "l"(v));
}
__device__ __forceinline__ unsigned long long dup_x2(float b) {
    unsigned long long r;
    asm("mov.b64 %0, {%1, %1};" : "=l"(r) : "f"(b));
    return r;
}

// monotonic float<->uint key (order-preserving under unsigned compare)
__device__ __forceinline__ uint32_t fkey(float f) {
    uint32_t b = __float_as_uint(f);
    return (b & 0x80000000u) ? ~b : (b | 0x80000000u);
}
__device__ __forceinline__ float finv(uint32_t u) {
    uint32_t b = (u & 0x80000000u) ? (u & 0x7fffffffu) : ~u;
    return __uint_as_float(b);
}

// ================= f32x2 SGEMM, BK=16 pipelined, 2 blocks/SM =================
// 128x128x16 tile, 256 threads, row-pair packed accumulators.
// One __syncthreads per 16-deep K-chunk; chain order identical (bit-exact).
// half_out: also emit half2 of the final values into g_zh (z_e launch only).
__global__ __launch_bounds__(256, 2) void sgemm_x2_nt_bias(
    const float* __restrict__ A, const float* __restrict__ Bm,
    const float* __restrict__ bias, float* __restrict__ C,
    int M, int N, int Kd, int half_out)
{
    const int BK = 16;
    __shared__ float As[2][BK][128];
    __shared__ float Bs[2][BK][128];

    int bm = blockIdx.y * 128, bn = blockIdx.x * 128;
    int tid = threadIdx.x;
    int tx = tid & 15, ty = tid >> 4;
    int lrow = tid >> 1, lk0 = (tid & 1) * 8;

    const float* Aptr = A  + (size_t)(bm + lrow) * Kd + lk0;
    const float* Bptr = Bm + (size_t)(bn + lrow) * Kd + lk0;

    unsigned long long acc2[4][8];   // [row-pair][col]
    #pragma unroll
    for (int rp = 0; rp < 4; rp++)
        #pragma unroll
        for (int j = 0; j < 8; j++) acc2[rp][j] = 0ull;

    const int NC = Kd / BK;

    // prologue: chunk 0 into stage 0
    {
        float4 a0 = *(const float4*)(Aptr);
        float4 a1 = *(const float4*)(Aptr + 4);
        float4 b0 = *(const float4*)(Bptr);
        float4 b1 = *(const float4*)(Bptr + 4);
        As[0][lk0 + 0][lrow] = a0.x; As[0][lk0 + 1][lrow] = a0.y;
        As[0][lk0 + 2][lrow] = a0.z; As[0][lk0 + 3][lrow] = a0.w;
        As[0][lk0 + 4][lrow] = a1.x; As[0][lk0 + 5][lrow] = a1.y;
        As[0][lk0 + 6][lrow] = a1.z; As[0][lk0 + 7][lrow] = a1.w;
        Bs[0][lk0 + 0][lrow] = b0.x; Bs[0][lk0 + 1][lrow] = b0.y;
        Bs[0][lk0 + 2][lrow] = b0.z; Bs[0][lk0 + 3][lrow] = b0.w;
        Bs[0][lk0 + 4][lrow] = b1.x; Bs[0][lk0 + 5][lrow] = b1.y;
        Bs[0][lk0 + 6][lrow] = b1.z; Bs[0][lk0 + 7][lrow] = b1.w;
    }
    __syncthreads();

    for (int c = 0; c < NC; c++) {
        int st = c & 1;
        float4 an0, an1, bn0, bn1;
        if (c + 1 < NC) {
            const float* Ap = Aptr + (c + 1) * BK;
            const float* Bp = Bptr + (c + 1) * BK;
            an0 = *(const float4*)(Ap);     an1 = *(const float4*)(Ap + 4);
            bn0 = *(const float4*)(Bp);     bn1 = *(const float4*)(Bp + 4);
        }
        #pragma unroll
        for (int kk = 0; kk < BK; kk++) {
            ulonglong2 a01 = *(const ulonglong2*)&As[st][kk][ty * 8];
            ulonglong2 a23 = *(const ulonglong2*)&As[st][kk][ty * 8 + 4];
            unsigned long long ap[4] = { a01.x, a01.y, a23.x, a23.y };
            float4 b0 = *(const float4*)&Bs[st][kk][tx * 8];
            float4 b1 = *(const float4*)&Bs[st][kk][tx * 8 + 4];
            unsigned long long bd[8];
            bd[0] = dup_x2(b0.x); bd[1] = dup_x2(b0.y);
            bd[2] = dup_x2(b0.z); bd[3] = dup_x2(b0.w);
            bd[4] = dup_x2(b1.x); bd[5] = dup_x2(b1.y);
            bd[6] = dup_x2(b1.z); bd[7] = dup_x2(b1.w);
            #pragma unroll
            for (int rp = 0; rp < 4; rp++)
                #pragma unroll
                for (int j = 0; j < 8; j++)
                    FMA_X2(acc2[rp][j], ap[rp], bd[j]);
        }
        if (c + 1 < NC) {
            int ns = (c + 1) & 1;
            As[ns][lk0 + 0][lrow] = an0.x; As[ns][lk0 + 1][lrow] = an0.y;
            As[ns][lk0 + 2][lrow] = an0.z; As[ns][lk0 + 3][lrow] = an0.w;
            As[ns][lk0 + 4][lrow] = an1.x; As[ns][lk0 + 5][lrow] = an1.y;
            As[ns][lk0 + 6][lrow] = an1.z; As[ns][lk0 + 7][lrow] = an1.w;
            Bs[ns][lk0 + 0][lrow] = bn0.x; Bs[ns][lk0 + 1][lrow] = bn0.y;
            Bs[ns][lk0 + 2][lrow] = bn0.z; Bs[ns][lk0 + 3][lrow] = bn0.w;
            Bs[ns][lk0 + 4][lrow] = bn1.x; Bs[ns][lk0 + 5][lrow] = bn1.y;
            Bs[ns][lk0 + 6][lrow] = bn1.z; Bs[ns][lk0 + 7][lrow] = bn1.w;
        }
        __syncthreads();
    }

    #pragma unroll
    for (int rp = 0; rp < 4; rp++) {
        int r0 = bm + ty * 8 + 2 * rp;
        int c = bn + tx * 8;
        float lo[8], hi[8];
        #pragma unroll
        for (int j = 0; j < 8; j++) unpack_x2(acc2[rp][j], lo[j], hi[j]);
        #pragma unroll
        for (int j = 0; j < 8; j++) {
            lo[j] += bias[c + j];
            hi[j] += bias[c + j];
        }
        *(float4*)&C[(size_t)r0 * N + c]     = make_float4(lo[0], lo[1], lo[2], lo[3]);
        *(float4*)&C[(size_t)r0 * N + c + 4] = make_float4(lo[4], lo[5], lo[6], lo[7]);
        *(float4*)&C[(size_t)(r0 + 1) * N + c]     = make_float4(hi[0], hi[1], hi[2], hi[3]);
        *(float4*)&C[(size_t)(r0 + 1) * N + c + 4] = make_float4(hi[4], hi[5], hi[6], hi[7]);
        if (half_out) {
            __half2* z0 = g_zh + (size_t)r0 * LW2 + (c >> 1);
            __half2* z1 = g_zh + (size_t)(r0 + 1) * LW2 + (c >> 1);
            #pragma unroll
            for (int t = 0; t < 4; t++) {
                z0[t] = __floats2half2_rn(lo[2 * t], lo[2 * t + 1]);
                z1[t] = __floats2half2_rn(hi[2 * t], hi[2 * t + 1]);
            }
        }
    }
}

// ================= half2 conversions =========================================
__global__ void cbhalf_kernel(const float* __restrict__ cb)
{
    size_t i = (size_t)blockIdx.x * blockDim.x + threadIdx.x;
    const float2 v = *(const float2*)(cb + i * 2);
    g_cbh[i] = __floats2half2_rn(v.x * 8192.0f, v.y * 8192.0f);
}

__global__ void init_rowmax_kernel(void)
{
    int i = blockIdx.x * blockDim.x + threadIdx.x;
    g_rowmax[i] = 0u;
}

// ================= half2 HFMA2 dot GEMM, BK=16 pipelined, 2 blocks/SM ========
__global__ __launch_bounds__(256, 2) void dist_h2_kernel(void)
{
    const int BK = 16;    // 16 half2 words = 32 halves per chunk
    __shared__ __half2   As[2][BK][128];
    __shared__ __half2   Bs[2][BK][128];
    __shared__ uint32_t  sv[128][16];

    int bm = blockIdx.y * 128, bn = blockIdx.x * 128;
    int tid = threadIdx.x;
    int tx = tid & 15, ty = tid >> 4;
    int lrow = tid >> 1, lk0 = (tid & 1) * 8;

    const __half2* Aptr = g_zh  + (size_t)(bm + lrow) * LW2 + lk0;
    const __half2* Bptr = g_cbh + (size_t)(bn + lrow) * LW2 + lk0;

    __half2 acc[8][8];
    #pragma unroll
    for (int i = 0; i < 8; i++)
        #pragma unroll
        for (int j = 0; j < 8; j++) acc[i][j] = __floats2half2_rn(0.f, 0.f);

    const int NC = LW2 / BK;   // 32

    // prologue
    {
        float4 a0f = *(const float4*)(Aptr);
        float4 a1f = *(const float4*)(Aptr + 4);
        float4 b0f = *(const float4*)(Bptr);
        float4 b1f = *(const float4*)(Bptr + 4);
        const __half2* a0 = (const __half2*)&a0f;
        const __half2* a1 = (const __half2*)&a1f;
        const __half2* b0 = (const __half2*)&b0f;
        const __half2* b1 = (const __half2*)&b1f;
        #pragma unroll
        for (int t = 0; t < 4; t++) {
            As[0][lk0 + t][lrow] = a0[t];  As[0][lk0 + 4 + t][lrow] = a1[t];
            Bs[0][lk0 + t][lrow] = b0[t];  Bs[0][lk0 + 4 + t][lrow] = b1[t];
        }
    }
    __syncthreads();

    for (int c = 0; c < NC; c++) {
        int st = c & 1;
        float4 anf0, anf1, bnf0, bnf1;
        if (c + 1 < NC) {
            const __half2* Ap = Aptr + (c + 1) * BK;
            const __half2* Bp = Bptr + (c + 1) * BK;
            anf0 = *(const float4*)(Ap);     anf1 = *(const float4*)(Ap + 4);
            bnf0 = *(const float4*)(Bp);     bnf1 = *(const float4*)(Bp + 4);
        }
        #pragma unroll
        for (int kk = 0; kk < BK; kk++) {
            __half2 ar[8], br[8];
            float4 a0f = *(const float4*)&As[st][kk][ty * 8];
            float4 a1f = *(const float4*)&As[st][kk][ty * 8 + 4];
            float4 b0f = *(const float4*)&Bs[st][kk][tx * 8];
            float4 b1f = *(const float4*)&Bs[st][kk][tx * 8 + 4];
            const __half2* a0 = (const __half2*)&a0f;
            const __half2* a1 = (const __half2*)&a1f;
            const __half2* b0 = (const __half2*)&b0f;
            const __half2* b1 = (const __half2*)&b1f;
            #pragma unroll
            for (int t = 0; t < 4; t++) { ar[t] = a0[t]; ar[t + 4] = a1[t]; }
            #pragma unroll
            for (int t = 0; t < 4; t++) { br[t] = b0[t]; br[t + 4] = b1[t]; }
            #pragma unroll
            for (int i = 0; i < 8; i++)
                #pragma unroll
                for (int j = 0; j < 8; j++)
                    acc[i][j] = __hfma2(ar[i], br[j], acc[i][j]);
        }
        if (c + 1 < NC) {
            int ns = (c + 1) & 1;
            const __half2* a0 = (const __half2*)&anf0;
            const __half2* a1 = (const __half2*)&anf1;
            const __half2* b0 = (const __half2*)&bnf0;
            const __half2* b1 = (const __half2*)&bnf1;
            #pragma unroll
            for (int t = 0; t < 4; t++) {
                As[ns][lk0 + t][lrow] = a0[t];  As[ns][lk0 + 4 + t][lrow] = a1[t];
                Bs[ns][lk0 + t][lrow] = b0[t];  Bs[ns][lk0 + 4 + t][lrow] = b1[t];
            }
        }
        __syncthreads();
    }

    #pragma unroll
    for (int i = 0; i < 8; i++) {
        int r = bm + ty * 8 + i;
        float f[8];
        #pragma unroll
        for (int j = 0; j < 8; j++)
            f[j] = __low2float(acc[i][j]) + __high2float(acc[i][j]);
        #pragma unroll
        for (int j = 0; j < 8; j += 4) {
            float4 o = make_float4(f[j], f[j + 1], f[j + 2], f[j + 3]);
            *(float4*)&g_dotf[(size_t)r * K_ + bn + tx * 8 + j] = o;
        }
        uint32_t rm = fkey(f[0]);
        #pragma unroll
        for (int j = 1; j < 8; j++) rm = max(rm, fkey(f[j]));
        sv[ty * 8 + i][tx] = rm;
    }
    __syncthreads();
    if (tid < 128) {
        uint32_t m = sv[tid][0];
        #pragma unroll
        for (int t = 1; t < 16; t++) m = max(m, sv[tid][t]);
        atomicMax(&g_rowmax[bm + tid], m);
    }
}

// ================= candidate collection (proven) ==============================
__global__ void scan_kernel(void)
{
    int w = threadIdx.x >> 5, lane = threadIdx.x & 31;
    int row = blockIdx.x * 8 + w;
    const float* d = g_dotf + (size_t)row * K_;

    float thr = finv(g_rowmax[row]) - WIN_DOTP;

    int cnt = 0;
    for (int j0 = 0; j0 < K_; j0 += 128) {
        float4 v = *(const float4*)(d + j0 + lane * 4);
        float dv[4] = { v.x, v.y, v.z, v.w };
        #pragma unroll
        for (int e = 0; e < 4; e++) {
            unsigned mask = __ballot_sync(0xffffffffu, dv[e] >= thr);
            if (dv[e] >= thr) {
                int slot = cnt + __popc(mask & ((1u << lane) - 1u));
                if (slot < CAND_MAX)
                    g_cand2[(size_t)row * CAND_MAX + slot] = j0 + lane * 4 + e;
            }
            cnt += __popc(mask);
        }
    }
    if (lane == 0) g_ncand[row] = cnt;
}

// ================= exact refinement (proven sequential-fp32 chain) ===========
__global__ void refine_kernel(const float* __restrict__ cb,
                              float* __restrict__ out_idx_f, int write_idx)
{
    int w = threadIdx.x >> 5, lane = threadIdx.x & 31;
    int row = blockIdx.x * 8 + w;
    const float* ze = g_ze + (size_t)row * L_;
    float P = g_P[row];
    int cnt = g_ncand[row];

    float bd = FLT_MAX; int bi = 0x7FFFFFFF;
    if (cnt <= CAND_MAX) {
        if (lane < cnt) {
            int col = g_cand2[(size_t)row * CAND_MAX + lane];
            const float* e = cb + (size_t)col * L_;
            float s = 0.0f;
            #pragma unroll 4
            for (int k = 0; k < L_; k++) s = fmaf(__ldg(&ze[k]), __ldg(&e[k]), s);
            float t = P - 2.0f * s;
            bd = t + __ldg(&g_c[col]);
            bi = col;
        }
    } else {
        for (int col = lane; col < K_; col += 32) {
            const float* e = cb + (size_t)col * L_;
            float s = 0.0f;
            #pragma unroll 4
            for (int k = 0; k < L_; k++) s = fmaf(__ldg(&ze[k]), __ldg(&e[k]), s);
            float t = P - 2.0f * s;
            float dv = t + __ldg(&g_c[col]);
            if (dv < bd || (dv == bd && col < bi)) { bd = dv; bi = col; }
        }
    }
    #pragma unroll
    for (int o = 16; o > 0; o >>= 1) {
        float od = __shfl_xor_sync(0xffffffffu, bd, o);
        int oi = __shfl_xor_sync(0xffffffffu, bi, o);
        if (od < bd || (od == bd && oi < bi)) { bd = od; bi = oi; }
    }
    if (lane == 0) {
        g_idx[row] = bi;
        if (write_idx) out_idx_f[row] = (float)bi;
    }
}

// ================= proven small kernels ======================================
__global__ void rowsumsq_kernel(const float* __restrict__ src, float* __restrict__ dst,
                                int rows, int cols)
{
    int row  = blockIdx.x * (blockDim.x >> 5) + (threadIdx.x >> 5);
    int lane = threadIdx.x & 31;
    if (row >= rows) return;
    const float* r = src + (size_t)row * cols;
    double s = 0.0;
    for (int j = lane; j < cols; j += 32) {
        float v = r[j];
        s += (double)v * (double)v;
    }
    #pragma unroll
    for (int o = 16; o > 0; o >>= 1) s += __shfl_down_sync(0xffffffffu, s, o);
    if (lane == 0) dst[row] = (float)s;
}

__global__ void loss_zq_kernel(const float* __restrict__ cb)
{
    int row = blockIdx.x;
    const float* ze = g_ze + (size_t)row * L_;
    const float* q  = cb   + (size_t)g_idx[row] * L_;
    float* zq = g_zq + (size_t)row * L_;
    double s = 0.0;
    for (int j = threadIdx.x; j < L_; j += blockDim.x) {
        float z = ze[j], qq = q[j];
        float dlt = qq - z;
        s += (double)dlt * (double)dlt;
        zq[j] = z + dlt;
    }
    __shared__ double sh[256];
    sh[threadIdx.x] = s;
    __syncthreads();
    for (int o = 128; o > 0; o >>= 1) {
        if (threadIdx.x < o) sh[threadIdx.x] += sh[threadIdx.x + o];
        __syncthreads();
    }
    if (threadIdx.x == 0) g_rowloss[row] = sh[0];
}

__global__ void loss_reduce_kernel(float* __restrict__ out_loss)
{
    __shared__ double sh[256];
    double s = 0.0;
    for (int r = threadIdx.x; r < B_; r += 256) s += g_rowloss[r];
    sh[threadIdx.x] = s;
    __syncthreads();
    for (int o = 128; o > 0; o >>= 1) {
        if (threadIdx.x < o) sh[threadIdx.x] += sh[threadIdx.x + o];
        __syncthreads();
    }
    if (threadIdx.x == 0) {
        float m = (float)(sh[0] / ((double)B_ * (double)L_));
        out_loss[0] = m + 0.25f * m;
    }
}

__global__ void softmax_kernel(float* __restrict__ logits)
{
    int row = blockIdx.x;
    float* p = logits + (size_t)row * O_;
    float v = p[threadIdx.x];
    __shared__ float shm[4];
    float m = v;
    #pragma unroll
    for (int o = 16; o > 0; o >>= 1) m = fmaxf(m, __shfl_xor_sync(0xffffffffu, m, o));
    if ((threadIdx.x & 31) == 0) shm[threadIdx.x >> 5] = m;
    __syncthreads();
    float mm = fmaxf(fmaxf(shm[0], shm[1]), fmaxf(shm[2], shm[3]));
    __syncthreads();
    float e = expf(v - mm);
    float s = e;
    #pragma unroll
    for (int o = 16; o > 0; o >>= 1) s += __shfl_xor_sync(0xffffffffu, s, o);
    if ((threadIdx.x & 31) == 0) shm[threadIdx.x >> 5] = s;
    __syncthreads();
    float ss = shm[0] + shm[1] + shm[2] + shm[3];
    p[threadIdx.x] = e / ss;
}

// ================= launch =====================================================
extern "C" void kernel_launch(void* const* d_in, const int* in_sizes, int n_in,
                              void* d_out, int out_size)
{
    const float* x     = (const float*)d_in[0];
    const float* W_enc = (const float*)d_in[1];
    const float* b_enc = (const float*)d_in[2];
    const float* cb    = (const float*)d_in[3];
    const float* W_cls = (const float*)d_in[4];
    const float* b_cls = (const float*)d_in[5];
    float* out = (float*)d_out;

    float* out_logits = out;
    float* out_loss   = out + (size_t)B_ * O_;
    float* out_idx    = out + (size_t)B_ * O_ + 1;
    int has_loss = (out_size >= B_ * O_ + 1);
    int has_idx  = (out_size >= B_ * O_ + 1 + B_);

    void *p;
    float *ze, *zq, *Pv, *cv;
    cudaGetSymbolAddress(&p, g_ze); ze = (float*)p;
    cudaGetSymbolAddress(&p, g_zq); zq = (float*)p;
    cudaGetSymbolAddress(&p, g_P);  Pv = (float*)p;
    cudaGetSymbolAddress(&p, g_c);  cv = (float*)p;

    // prep: codebook norms + scaled half2 codebook
    rowsumsq_kernel<<<K_ / 8, 256>>>(cb, cv, K_, L_);
    cbhalf_kernel<<<(unsigned)((size_t)K_ * LW2 / 256), 256>>>(cb);
    init_rowmax_kernel<<<B_ / 256, 256>>>();

    // z_e = x @ W_enc^T + b_enc  (BK=16 f32x2, fused half2 output)
    {
        dim3 grid(L_ / 128, B_ / 128);
        sgemm_x2_nt_bias<<<grid, 256>>>(x, W_enc, b_enc, ze, B_, L_, TD_, 1);
    }
    rowsumsq_kernel<<<B_ / 8, 256>>>(ze, Pv, B_, L_);

    // half2 HFMA2 dot GEMM (BK=16) + rowmax, then collect + exact refine
    {
        dim3 grid(K_ / 128, B_ / 128);
        dist_h2_kernel<<<grid, 256>>>();
    }
    scan_kernel<<<B_ / 8, 256>>>();
    refine_kernel<<<B_ / 8, 256>>>(cb, out_idx, has_idx);

    // loss + z_q (proven path)
    loss_zq_kernel<<<B_, 256>>>(cb);
    if (has_loss) loss_reduce_kernel<<<1, 256>>>(out_loss);

    // classifier + softmax
    {
        dim3 grid(O_ / 128, B_ / 128);
        sgemm_x2_nt_bias<<<grid, 256>>>(zq, W_cls, b_cls, out_logits, B_, O_, L_, 0);
    }
    softmax_kernel<<<B_, 128>>>(out_logits);
}

// round 15
// speedup vs baseline: 1.0268x; 1.0268x over previous
#include <cuda_runtime.h>
#include <cuda_fp16.h>
#include <cstdint>
#include <cfloat>

#define B_  16384
#define TD_ 4096
#define L_  1024
#define K_  8192
#define O_  128
#define LW2 (L_ / 2)          // 512 half2 words per row

#define CAND_MAX 16
#define WIN_DOTP 2.0f         // capture window in scaled-dot units (8192*dot)

// ---------------- scratch (device globals) -----------------------------------
__device__ float    g_ze[(size_t)B_ * L_];      // 64 MB fp32 z_e
__device__ float    g_zq[(size_t)B_ * L_];      // 64 MB fp32 z_q
__device__ float    g_dotf[(size_t)B_ * K_];    // 512 MB scaled approx dots
__device__ __half2  g_zh[(size_t)B_ * LW2];     // 32 MB packed half2 z
__device__ __half2  g_cbh[(size_t)K_ * LW2];    // 16 MB packed half2 codebook*8192
__device__ float    g_P[B_];
__device__ float    g_c[K_];
__device__ uint32_t g_rowmax[B_];               // monotonic float keys
__device__ int      g_idx[B_];
__device__ int      g_cand2[(size_t)B_ * CAND_MAX];
__device__ int      g_ncand[B_];
__device__ double   g_rowloss[B_];

// packed fp32x2 FMA: two IEEE-rn fp32 FMAs per instruction (sm_100+)
#define FMA_X2(acc, a, b) \
    asm("fma.rn.f32x2 %0, %1, %2, %0;" : "+l"(acc) : "l"(a), "l"(b))
__device__ __forceinline__ void unpack_x2(unsigned long long v, float& lo, float& hi) {
    asm("mov.b64 {%0, %1}, %2;" : "=f"(lo), "=f"(hi) : "l"(v));
}
__device__ __forceinline__ unsigned long long dup_x2(float b) {
    unsigned long long r;
    asm("mov.b64 %0, {%1, %1};" : "=l"(r) : "f"(b));
    return r;
}

// monotonic float<->uint key (order-preserving under unsigned compare)
__device__ __forceinline__ uint32_t fkey(float f) {
    uint32_t b = __float_as_uint(f);
    return (b & 0x80000000u) ? ~b : (b | 0x80000000u);
}
__device__ __forceinline__ float finv(uint32_t u) {
    uint32_t b = (u & 0x80000000u) ? (u & 0x7fffffffu) : ~u;
    return __uint_as_float(b);
}

// ================= f32x2 SGEMM, 256x128 tile, 16x8 micro-tile ================
// 256 threads; thread tile = 16 rows (8 row-pairs, b64 direct from smem) x 8 cols.
// Per block-kk: FMA 256 cyc vs LDS 192 cyc -> FMA-bound (25% crossbar headroom).
// Per-output accumulation chain sequential over k (bit-exact vs scalar FFMA).
// half_out: also emit half2 of the final values into g_zh (z_e launch only).
__global__ __launch_bounds__(256) void sgemm_x2_nt_bias(
    const float* __restrict__ A, const float* __restrict__ Bm,
    const float* __restrict__ bias, float* __restrict__ C,
    int M, int N, int Kd, int half_out)
{
    const int BK = 8;
    __shared__ float As[2][BK][256];
    __shared__ float Bs[2][BK][128];

    int bm = blockIdx.y * 256, bn = blockIdx.x * 128;
    int tid = threadIdx.x;
    int tx = tid & 15, ty = tid >> 4;      // ty: 16-row group, tx: 8-col group

    const float* Aptr = A + (size_t)(bm + tid) * Kd;           // one row per thread
    int brow = tid >> 1, bk = (tid & 1) * 4;
    const float* Bptr = Bm + (size_t)(bn + brow) * Kd + bk;

    unsigned long long acc2[8][8];   // [row-pair][col]
    #pragma unroll
    for (int rp = 0; rp < 8; rp++)
        #pragma unroll
        for (int j = 0; j < 8; j++) acc2[rp][j] = 0ull;

    const int NC = Kd / BK;

    // prologue: chunk 0 into stage 0
    {
        float4 a0 = *(const float4*)(Aptr);
        float4 a1 = *(const float4*)(Aptr + 4);
        float4 b  = *(const float4*)(Bptr);
        As[0][0][tid] = a0.x; As[0][1][tid] = a0.y;
        As[0][2][tid] = a0.z; As[0][3][tid] = a0.w;
        As[0][4][tid] = a1.x; As[0][5][tid] = a1.y;
        As[0][6][tid] = a1.z; As[0][7][tid] = a1.w;
        Bs[0][bk + 0][brow] = b.x; Bs[0][bk + 1][brow] = b.y;
        Bs[0][bk + 2][brow] = b.z; Bs[0][bk + 3][brow] = b.w;
    }
    __syncthreads();

    for (int c = 0; c < NC; c++) {
        int st = c & 1;
        float4 an0, an1, bn2;
        if (c + 1 < NC) {
            const float* Ap = Aptr + (c + 1) * BK;
            an0 = *(const float4*)(Ap);
            an1 = *(const float4*)(Ap + 4);
            bn2 = *(const float4*)(Bptr + (c + 1) * BK);
        }
        #pragma unroll
        for (int kk = 0; kk < BK; kk++) {
            // A: 8 row-pairs, direct b64 from transposed smem (broadcast loads)
            ulonglong2 A0 = *(const ulonglong2*)&As[st][kk][ty * 16];
            ulonglong2 A1 = *(const ulonglong2*)&As[st][kk][ty * 16 + 4];
            ulonglong2 A2 = *(const ulonglong2*)&As[st][kk][ty * 16 + 8];
            ulonglong2 A3 = *(const ulonglong2*)&As[st][kk][ty * 16 + 12];
            unsigned long long ap[8] = { A0.x, A0.y, A1.x, A1.y,
                                         A2.x, A2.y, A3.x, A3.y };
            float4 b0 = *(const float4*)&Bs[st][kk][tx * 8];
            float4 b1 = *(const float4*)&Bs[st][kk][tx * 8 + 4];
            unsigned long long bd[8];
            bd[0] = dup_x2(b0.x); bd[1] = dup_x2(b0.y);
            bd[2] = dup_x2(b0.z); bd[3] = dup_x2(b0.w);
            bd[4] = dup_x2(b1.x); bd[5] = dup_x2(b1.y);
            bd[6] = dup_x2(b1.z); bd[7] = dup_x2(b1.w);
            #pragma unroll
            for (int rp = 0; rp < 8; rp++)
                #pragma unroll
                for (int j = 0; j < 8; j++)
                    FMA_X2(acc2[rp][j], ap[rp], bd[j]);
        }
        if (c + 1 < NC) {
            int ns = (c + 1) & 1;
            As[ns][0][tid] = an0.x; As[ns][1][tid] = an0.y;
            As[ns][2][tid] = an0.z; As[ns][3][tid] = an0.w;
            As[ns][4][tid] = an1.x; As[ns][5][tid] = an1.y;
            As[ns][6][tid] = an1.z; As[ns][7][tid] = an1.w;
            Bs[ns][bk + 0][brow] = bn2.x; Bs[ns][bk + 1][brow] = bn2.y;
            Bs[ns][bk + 2][brow] = bn2.z; Bs[ns][bk + 3][brow] = bn2.w;
        }
        __syncthreads();
    }

    #pragma unroll
    for (int rp = 0; rp < 8; rp++) {
        int r0 = bm + ty * 16 + 2 * rp;
        int c = bn + tx * 8;
        float lo[8], hi[8];
        #pragma unroll
        for (int j = 0; j < 8; j++) unpack_x2(acc2[rp][j], lo[j], hi[j]);
        #pragma unroll
        for (int j = 0; j < 8; j++) {
            lo[j] += bias[c + j];
            hi[j] += bias[c + j];
        }
        *(float4*)&C[(size_t)r0 * N + c]     = make_float4(lo[0], lo[1], lo[2], lo[3]);
        *(float4*)&C[(size_t)r0 * N + c + 4] = make_float4(lo[4], lo[5], lo[6], lo[7]);
        *(float4*)&C[(size_t)(r0 + 1) * N + c]     = make_float4(hi[0], hi[1], hi[2], hi[3]);
        *(float4*)&C[(size_t)(r0 + 1) * N + c + 4] = make_float4(hi[4], hi[5], hi[6], hi[7]);
        if (half_out) {
            __half2* z0 = g_zh + (size_t)r0 * LW2 + (c >> 1);
            __half2* z1 = g_zh + (size_t)(r0 + 1) * LW2 + (c >> 1);
            #pragma unroll
            for (int t = 0; t < 4; t++) {
                z0[t] = __floats2half2_rn(lo[2 * t], lo[2 * t + 1]);
                z1[t] = __floats2half2_rn(hi[2 * t], hi[2 * t + 1]);
            }
        }
    }
}

// ================= half2 conversions =========================================
__global__ void cbhalf_kernel(const float* __restrict__ cb)
{
    size_t i = (size_t)blockIdx.x * blockDim.x + threadIdx.x;
    const float2 v = *(const float2*)(cb + i * 2);
    g_cbh[i] = __floats2half2_rn(v.x * 8192.0f, v.y * 8192.0f);
}

__global__ void init_rowmax_kernel(void)
{
    int i = blockIdx.x * blockDim.x + threadIdx.x;
    g_rowmax[i] = 0u;
}

// ================= half2 HFMA2 dot GEMM, BK=16 pipelined, 2 blocks/SM ========
// (R13/R14 proven; at its fma-pipe floor — untouched)
__global__ __launch_bounds__(256, 2) void dist_h2_kernel(void)
{
    const int BK = 16;    // 16 half2 words = 32 halves per chunk
    __shared__ __half2   As[2][BK][128];
    __shared__ __half2   Bs[2][BK][128];
    __shared__ uint32_t  sv[128][16];

    int bm = blockIdx.y * 128, bn = blockIdx.x * 128;
    int tid = threadIdx.x;
    int tx = tid & 15, ty = tid >> 4;
    int lrow = tid >> 1, lk0 = (tid & 1) * 8;

    const __half2* Aptr = g_zh  + (size_t)(bm + lrow) * LW2 + lk0;
    const __half2* Bptr = g_cbh + (size_t)(bn + lrow) * LW2 + lk0;

    __half2 acc[8][8];
    #pragma unroll
    for (int i = 0; i < 8; i++)
        #pragma unroll
        for (int j = 0; j < 8; j++) acc[i][j] = __floats2half2_rn(0.f, 0.f);

    const int NC = LW2 / BK;   // 32

    // prologue
    {
        float4 a0f = *(const float4*)(Aptr);
        float4 a1f = *(const float4*)(Aptr + 4);
        float4 b0f = *(const float4*)(Bptr);
        float4 b1f = *(const float4*)(Bptr + 4);
        const __half2* a0 = (const __half2*)&a0f;
        const __half2* a1 = (const __half2*)&a1f;
        const __half2* b0 = (const __half2*)&b0f;
        const __half2* b1 = (const __half2*)&b1f;
        #pragma unroll
        for (int t = 0; t < 4; t++) {
            As[0][lk0 + t][lrow] = a0[t];  As[0][lk0 + 4 + t][lrow] = a1[t];
            Bs[0][lk0 + t][lrow] = b0[t];  Bs[0][lk0 + 4 + t][lrow] = b1[t];
        }
    }
    __syncthreads();

    for (int c = 0; c < NC; c++) {
        int st = c & 1;
        float4 anf0, anf1, bnf0, bnf1;
        if (c + 1 < NC) {
            const __half2* Ap = Aptr + (c + 1) * BK;
            const __half2* Bp = Bptr + (c + 1) * BK;
            anf0 = *(const float4*)(Ap);     anf1 = *(const float4*)(Ap + 4);
            bnf0 = *(const float4*)(Bp);     bnf1 = *(const float4*)(Bp + 4);
        }
        #pragma unroll
        for (int kk = 0; kk < BK; kk++) {
            __half2 ar[8], br[8];
            float4 a0f = *(const float4*)&As[st][kk][ty * 8];
            float4 a1f = *(const float4*)&As[st][kk][ty * 8 + 4];
            float4 b0f = *(const float4*)&Bs[st][kk][tx * 8];
            float4 b1f = *(const float4*)&Bs[st][kk][tx * 8 + 4];
            const __half2* a0 = (const __half2*)&a0f;
            const __half2* a1 = (const __half2*)&a1f;
            const __half2* b0 = (const __half2*)&b0f;
            const __half2* b1 = (const __half2*)&b1f;
            #pragma unroll
            for (int t = 0; t < 4; t++) { ar[t] = a0[t]; ar[t + 4] = a1[t]; }
            #pragma unroll
            for (int t = 0; t < 4; t++) { br[t] = b0[t]; br[t + 4] = b1[t]; }
            #pragma unroll
            for (int i = 0; i < 8; i++)
                #pragma unroll
                for (int j = 0; j < 8; j++)
                    acc[i][j] = __hfma2(ar[i], br[j], acc[i][j]);
        }
        if (c + 1 < NC) {
            int ns = (c + 1) & 1;
            const __half2* a0 = (const __half2*)&anf0;
            const __half2* a1 = (const __half2*)&anf1;
            const __half2* b0 = (const __half2*)&bnf0;
            const __half2* b1 = (const __half2*)&bnf1;
            #pragma unroll
            for (int t = 0; t < 4; t++) {
                As[ns][lk0 + t][lrow] = a0[t];  As[ns][lk0 + 4 + t][lrow] = a1[t];
                Bs[ns][lk0 + t][lrow] = b0[t];  Bs[ns][lk0 + 4 + t][lrow] = b1[t];
            }
        }
        __syncthreads();
    }

    #pragma unroll
    for (int i = 0; i < 8; i++) {
        int r = bm + ty * 8 + i;
        float f[8];
        #pragma unroll
        for (int j = 0; j < 8; j++)
            f[j] = __low2float(acc[i][j]) + __high2float(acc[i][j]);
        #pragma unroll
        for (int j = 0; j < 8; j += 4) {
            float4 o = make_float4(f[j], f[j + 1], f[j + 2], f[j + 3]);
            *(float4*)&g_dotf[(size_t)r * K_ + bn + tx * 8 + j] = o;
        }
        uint32_t rm = fkey(f[0]);
        #pragma unroll
        for (int j = 1; j < 8; j++) rm = max(rm, fkey(f[j]));
        sv[ty * 8 + i][tx] = rm;
    }
    __syncthreads();
    if (tid < 128) {
        uint32_t m = sv[tid][0];
        #pragma unroll
        for (int t = 1; t < 16; t++) m = max(m, sv[tid][t]);
        atomicMax(&g_rowmax[bm + tid], m);
    }
}

// ================= candidate collection (proven) ==============================
__global__ void scan_kernel(void)
{
    int w = threadIdx.x >> 5, lane = threadIdx.x & 31;
    int row = blockIdx.x * 8 + w;
    const float* d = g_dotf + (size_t)row * K_;

    float thr = finv(g_rowmax[row]) - WIN_DOTP;

    int cnt = 0;
    for (int j0 = 0; j0 < K_; j0 += 128) {
        float4 v = *(const float4*)(d + j0 + lane * 4);
        float dv[4] = { v.x, v.y, v.z, v.w };
        #pragma unroll
        for (int e = 0; e < 4; e++) {
            unsigned mask = __ballot_sync(0xffffffffu, dv[e] >= thr);
            if (dv[e] >= thr) {
                int slot = cnt + __popc(mask & ((1u << lane) - 1u));
                if (slot < CAND_MAX)
                    g_cand2[(size_t)row * CAND_MAX + slot] = j0 + lane * 4 + e;
            }
            cnt += __popc(mask);
        }
    }
    if (lane == 0) g_ncand[row] = cnt;
}

// ================= exact refinement (proven sequential-fp32 chain) ===========
__global__ void refine_kernel(const float* __restrict__ cb,
                              float* __restrict__ out_idx_f, int write_idx)
{
    int w = threadIdx.x >> 5, lane = threadIdx.x & 31;
    int row = blockIdx.x * 8 + w;
    const float* ze = g_ze + (size_t)row * L_;
    float P = g_P[row];
    int cnt = g_ncand[row];

    float bd = FLT_MAX; int bi = 0x7FFFFFFF;
    if (cnt <= CAND_MAX) {
        if (lane < cnt) {
            int col = g_cand2[(size_t)row * CAND_MAX + lane];
            const float* e = cb + (size_t)col * L_;
            float s = 0.0f;
            #pragma unroll 4
            for (int k = 0; k < L_; k++) s = fmaf(__ldg(&ze[k]), __ldg(&e[k]), s);
            float t = P - 2.0f * s;
            bd = t + __ldg(&g_c[col]);
            bi = col;
        }
    } else {
        for (int col = lane; col < K_; col += 32) {
            const float* e = cb + (size_t)col * L_;
            float s = 0.0f;
            #pragma unroll 4
            for (int k = 0; k < L_; k++) s = fmaf(__ldg(&ze[k]), __ldg(&e[k]), s);
            float t = P - 2.0f * s;
            float dv = t + __ldg(&g_c[col]);
            if (dv < bd || (dv == bd && col < bi)) { bd = dv; bi = col; }
        }
    }
    #pragma unroll
    for (int o = 16; o > 0; o >>= 1) {
        float od = __shfl_xor_sync(0xffffffffu, bd, o);
        int oi = __shfl_xor_sync(0xffffffffu, bi, o);
        if (od < bd || (od == bd && oi < bi)) { bd = od; bi = oi; }
    }
    if (lane == 0) {
        g_idx[row] = bi;
        if (write_idx) out_idx_f[row] = (float)bi;
    }
}

// ================= proven small kernels ======================================
__global__ void rowsumsq_kernel(const float* __restrict__ src, float* __restrict__ dst,
                                int rows, int cols)
{
    int row  = blockIdx.x * (blockDim.x >> 5) + (threadIdx.x >> 5);
    int lane = threadIdx.x & 31;
    if (row >= rows) return;
    const float* r = src + (size_t)row * cols;
    double s = 0.0;
    for (int j = lane; j < cols; j += 32) {
        float v = r[j];
        s += (double)v * (double)v;
    }
    #pragma unroll
    for (int o = 16; o > 0; o >>= 1) s += __shfl_down_sync(0xffffffffu, s, o);
    if (lane == 0) dst[row] = (float)s;
}

__global__ void loss_zq_kernel(const float* __restrict__ cb)
{
    int row = blockIdx.x;
    const float* ze = g_ze + (size_t)row * L_;
    const float* q  = cb   + (size_t)g_idx[row] * L_;
    float* zq = g_zq + (size_t)row * L_;
    double s = 0.0;
    for (int j = threadIdx.x; j < L_; j += blockDim.x) {
        float z = ze[j], qq = q[j];
        float dlt = qq - z;
        s += (double)dlt * (double)dlt;
        zq[j] = z + dlt;
    }
    __shared__ double sh[256];
    sh[threadIdx.x] = s;
    __syncthreads();
    for (int o = 128; o > 0; o >>= 1) {
        if (threadIdx.x < o) sh[threadIdx.x] += sh[threadIdx.x + o];
        __syncthreads();
    }
    if (threadIdx.x == 0) g_rowloss[row] = sh[0];
}

__global__ void loss_reduce_kernel(float* __restrict__ out_loss)
{
    __shared__ double sh[256];
    double s = 0.0;
    for (int r = threadIdx.x; r < B_; r += 256) s += g_rowloss[r];
    sh[threadIdx.x] = s;
    __syncthreads();
    for (int o = 128; o > 0; o >>= 1) {
        if (threadIdx.x < o) sh[threadIdx.x] += sh[threadIdx.x + o];
        __syncthreads();
    }
    if (threadIdx.x == 0) {
        float m = (float)(sh[0] / ((double)B_ * (double)L_));
        out_loss[0] = m + 0.25f * m;
    }
}

__global__ void softmax_kernel(float* __restrict__ logits)
{
    int row = blockIdx.x;
    float* p = logits + (size_t)row * O_;
    float v = p[threadIdx.x];
    __shared__ float shm[4];
    float m = v;
    #pragma unroll
    for (int o = 16; o > 0; o >>= 1) m = fmaxf(m, __shfl_xor_sync(0xffffffffu, m, o));
    if ((threadIdx.x & 31) == 0) shm[threadIdx.x >> 5] = m;
    __syncthreads();
    float mm = fmaxf(fmaxf(shm[0], shm[1]), fmaxf(shm[2], shm[3]));
    __syncthreads();
    float e = expf(v - mm);
    float s = e;
    #pragma unroll
    for (int o = 16; o > 0; o >>= 1) s += __shfl_xor_sync(0xffffffffu, s, o);
    if ((threadIdx.x & 31) == 0) shm[threadIdx.x >> 5] = s;
    __syncthreads();
    float ss = shm[0] + shm[1] + shm[2] + shm[3];
    p[threadIdx.x] = e / ss;
}

// ================= launch =====================================================
extern "C" void kernel_launch(void* const* d_in, const int* in_sizes, int n_in,
                              void* d_out, int out_size)
{
    const float* x     = (const float*)d_in[0];
    const float* W_enc = (const float*)d_in[1];
    const float* b_enc = (const float*)d_in[2];
    const float* cb    = (const float*)d_in[3];
    const float* W_cls = (const float*)d_in[4];
    const float* b_cls = (const float*)d_in[5];
    float* out = (float*)d_out;

    float* out_logits = out;
    float* out_loss   = out + (size_t)B_ * O_;
    float* out_idx    = out + (size_t)B_ * O_ + 1;
    int has_loss = (out_size >= B_ * O_ + 1);
    int has_idx  = (out_size >= B_ * O_ + 1 + B_);

    void *p;
    float *ze, *zq, *Pv, *cv;
    cudaGetSymbolAddress(&p, g_ze); ze = (float*)p;
    cudaGetSymbolAddress(&p, g_zq); zq = (float*)p;
    cudaGetSymbolAddress(&p, g_P);  Pv = (float*)p;
    cudaGetSymbolAddress(&p, g_c);  cv = (float*)p;

    // prep: codebook norms + scaled half2 codebook
    rowsumsq_kernel<<<K_ / 8, 256>>>(cb, cv, K_, L_);
    cbhalf_kernel<<<(unsigned)((size_t)K_ * LW2 / 256), 256>>>(cb);
    init_rowmax_kernel<<<B_ / 256, 256>>>();

    // z_e = x @ W_enc^T + b_enc  (256x128 tile f32x2, fused half2 output)
    {
        dim3 grid(L_ / 128, B_ / 256);
        sgemm_x2_nt_bias<<<grid, 256>>>(x, W_enc, b_enc, ze, B_, L_, TD_, 1);
    }
    rowsumsq_kernel<<<B_ / 8, 256>>>(ze, Pv, B_, L_);

    // half2 HFMA2 dot GEMM (BK=16) + rowmax, then collect + exact refine
    {
        dim3 grid(K_ / 128, B_ / 128);
        dist_h2_kernel<<<grid, 256>>>();
    }
    scan_kernel<<<B_ / 8, 256>>>();
    refine_kernel<<<B_ / 8, 256>>>(cb, out_idx, has_idx);

    // loss + z_q (proven path)
    loss_zq_kernel<<<B_, 256>>>(cb);
    if (has_loss) loss_reduce_kernel<<<1, 256>>>(out_loss);

    // classifier + softmax
    {
        dim3 grid(O_ / 128, B_ / 256);
        sgemm_x2_nt_bias<<<grid, 256>>>(zq, W_cls, b_cls, out_logits, B_, O_, L_, 0);
    }
    softmax_kernel<<<B_, 128>>>(out_logits);
}